// round 11
// baseline (speedup 1.0000x reference)
#include <cuda_runtime.h>
#include <cstdint>

typedef unsigned long long u64;

#define IMG_W 512
#define IMG_H 512

#define TILE_OROWS 8            // output rows per CTA
#define SROWS 12                // input rows staged (8 + 4 halo)
#define SSTRIDE 520             // floats per smem row (2080 B, 8B-aligned)

// XOR bank swizzle: kills the 4-way conflicts of 8B accesses at 16B lane
// stride. XORs addr bits [5:4] with [8:7]; preserves 8B granules.
__device__ __forceinline__ int swz(int off) {
    return off ^ ((off >> 3) & 0x30);
}

// ---- f32x2 packed helpers ----
__device__ __forceinline__ u64 pack2(float lo, float hi) {
    u64 r;
    asm("mov.b64 %0, {%1, %2};"
        : "=l"(r) : "r"(__float_as_uint(lo)), "r"(__float_as_uint(hi)));
    return r;
}

__device__ __forceinline__ void fma2(u64& d, u64 a, u64 b) {
    asm("fma.rn.f32x2 %0, %1, %2, %0;" : "+l"(d) : "l"(a), "l"(b));
}

// (hi(a), lo(b)) -> odd-aligned sliding pair (2 MOVs in SASS).
__device__ __forceinline__ u64 pack_hl(u64 a, u64 b) {
    u64 d;
    asm("{\n\t"
        ".reg .b32 al, ah, bl, bh;\n\t"
        "mov.b64 {al, ah}, %1;\n\t"
        "mov.b64 {bl, bh}, %2;\n\t"
        "mov.b64 %0, {ah, bl};\n\t"
        "}" : "=l"(d) : "l"(a), "l"(b));
    return d;
}

// CTA: 256 threads. Stage a 12-row x 516-col zero-padded input tile in smem
// (6 independent LDG.128/thread), then feed all conv FMAs from
// bank-conflict-free (swizzled) LDS.64. Thread: 4 out rows x 4 out cols.
__global__ __launch_bounds__(256)
void conv5x5_smem_kernel(const float* __restrict__ X,
                         const float* __restrict__ K,
                         float* __restrict__ O) {
    __shared__ __align__(16) float smem[SROWS * SSTRIDE];

    const int tid  = threadIdx.x;
    const int tx   = tid & 127;
    const int tg   = tid >> 7;
    const int col  = tx << 2;
    const int img  = blockIdx.y;
    const int row0 = blockIdx.x << 3;          // CTA's first output row

    const float* in = X + (size_t)img * (IMG_W * IMG_H);
    char* sbase = reinterpret_cast<char*>(smem);

    // ---- Stage 1: burst-load tile (rows row0-2 .. row0+9), zero-filled OOB.
    // cpad = image_col + 2; within-row byte offset = cpad*4, swizzled.
    #pragma unroll
    for (int i = 0; i < 6; i++) {
        const int q  = tid + (i << 8);
        const int r  = q >> 7;                  // 0..11
        const int c4 = (q & 127) << 4;          // byte offset of image col c
        const int gr = row0 - 2 + r;
        float4 v = make_float4(0.f, 0.f, 0.f, 0.f);
        if (gr >= 0 && gr < IMG_H)
            v = *reinterpret_cast<const float4*>(
                    in + (size_t)gr * IMG_W + ((q & 127) << 2));
        char* rowp = sbase + r * (SSTRIDE * 4);
        *reinterpret_cast<u64*>(rowp + swz(c4 + 8))  = pack2(v.x, v.y);
        *reinterpret_cast<u64*>(rowp + swz(c4 + 16)) = pack2(v.z, v.w);
    }
    // halo columns: cpad {0,1} (byte 0) and {514,515} (byte 2056) are zero
    if (tid < 24) {
        const int r   = tid < 12 ? tid : tid - 12;
        const int off = tid < 12 ? swz(0) : swz(2056);
        *reinterpret_cast<u64*>(sbase + r * (SSTRIDE * 4) + off) = 0ull;
    }

    // Broadcast-packed weights (w,w) x25 (overlaps the smem fill).
    u64 wp[25];
    {
        const float4* K4 = reinterpret_cast<const float4*>(K);
        #pragma unroll
        for (int i = 0; i < 6; i++) {
            float4 v = __ldg(K4 + i);
            wp[4*i+0] = pack2(v.x, v.x);
            wp[4*i+1] = pack2(v.y, v.y);
            wp[4*i+2] = pack2(v.z, v.z);
            wp[4*i+3] = pack2(v.w, v.w);
        }
        float w24 = __ldg(K + 24);
        wp[24] = pack2(w24, w24);
    }

    __syncthreads();

    // ---- Stage 2: conv from smem, swizzled conflict-free LDS.64.
    u64 acc[4][2];
    #pragma unroll
    for (int ro = 0; ro < 4; ro++) { acc[ro][0] = 0ull; acc[ro][1] = 0ull; }

    const int cb = tx << 4;                    // byte offset of cpad col `col`
    #pragma unroll
    for (int lr = 0; lr < 8; lr++) {
        const char* rowp = sbase + ((tg << 2) + lr) * (SSTRIDE * 4);
        u64 p0 = *reinterpret_cast<const u64*>(rowp + swz(cb));       // x[c-2],x[c-1]
        u64 p2 = *reinterpret_cast<const u64*>(rowp + swz(cb + 8));   // x[c],  x[c+1]
        u64 p4 = *reinterpret_cast<const u64*>(rowp + swz(cb + 16));  // x[c+2],x[c+3]
        u64 p6 = *reinterpret_cast<const u64*>(rowp + swz(cb + 24));  // x[c+4],x[c+5]
        u64 p1 = pack_hl(p0, p2);
        u64 p3 = pack_hl(p2, p4);
        u64 p5 = pack_hl(p4, p6);
        u64 p[7] = {p0, p1, p2, p3, p4, p5, p6};

        // input row lr feeds output rows ro with kr = lr - ro in [0,4]
        #pragma unroll
        for (int ro = 0; ro < 4; ro++) {
            const int kr = lr - ro;
            if (kr < 0 || kr > 4) continue;
            #pragma unroll
            for (int kc = 0; kc < 5; kc++) {
                fma2(acc[ro][0], p[kc],     wp[kr*5 + kc]);  // (col, col+1)
                fma2(acc[ro][1], p[kc + 2], wp[kr*5 + kc]);  // (col+2, col+3)
            }
        }
    }

    float* op = O + (size_t)img * (IMG_W * IMG_H)
                  + (size_t)(row0 + (tg << 2)) * IMG_W + col;
    #pragma unroll
    for (int ro = 0; ro < 4; ro++) {
        ulonglong2 v;
        v.x = acc[ro][0];
        v.y = acc[ro][1];
        *reinterpret_cast<ulonglong2*>(op + (size_t)ro * IMG_W) = v;  // STG.128
    }
}

extern "C" void kernel_launch(void* const* d_in, const int* in_sizes, int n_in,
                              void* d_out, int out_size) {
    const float* X = (const float*)d_in[0];   // (4,32,512,512) f32
    const float* K = (const float*)d_in[1];   // (5,5) f32
    float* O = (float*)d_out;                 // (4,32,512,512) f32
    (void)in_sizes; (void)n_in; (void)out_size;  // stride=1, padding=2 fixed

    dim3 grid(IMG_H / TILE_OROWS, 4 * 32);    // 64 row tiles x 128 images
    conv5x5_smem_kernel<<<grid, 256>>>(X, K, O);
}

// round 13
// speedup vs baseline: 1.1792x; 1.1792x over previous
#include <cuda_runtime.h>
#include <cstdint>

typedef unsigned long long u64;

#define IMG_W 512
#define IMG_H 512

#define TILE_OROWS 8            // output rows per CTA
#define SROWS 12                // input rows staged (8 + 4 halo)
#define SPAD  4                 // left-pad floats: cpad = c + 4 (16B shift)
#define SWIDTH (SPAD + IMG_W + SPAD)   // 520 floats
#define SROWB (SWIDTH * 4)             // 2080 bytes, multiple of 16

// ---- f32x2 packed helpers ----
__device__ __forceinline__ u64 pack2(float lo, float hi) {
    u64 r;
    asm("mov.b64 %0, {%1, %2};"
        : "=l"(r) : "r"(__float_as_uint(lo)), "r"(__float_as_uint(hi)));
    return r;
}

__device__ __forceinline__ void fma2(u64& d, u64 a, u64 b) {
    asm("fma.rn.f32x2 %0, %1, %2, %0;" : "+l"(d) : "l"(a), "l"(b));
}

// (hi(a), lo(b)) -> odd-aligned sliding pair (2 MOVs in SASS).
__device__ __forceinline__ u64 pack_hl(u64 a, u64 b) {
    u64 d;
    asm("{\n\t"
        ".reg .b32 al, ah, bl, bh;\n\t"
        "mov.b64 {al, ah}, %1;\n\t"
        "mov.b64 {bl, bh}, %2;\n\t"
        "mov.b64 %0, {ah, bl};\n\t"
        "}" : "=l"(d) : "l"(a), "l"(b));
    return d;
}

// CTA: 256 threads. Stage a 12-row x (4+512+4)-col zero-padded tile in smem.
// The 4-float left pad makes every thread's 8-float read window start at a
// 16B-aligned offset (byte 16*tx): stores are clean STS.128, and the center
// quad is a clean LDS.128; only the two 8B edge loads are 2-way conflicted.
// Thread computes 4 out rows x 4 out cols with packed f32x2 FMAs.
__global__ __launch_bounds__(256)
void conv5x5_smem_kernel(const float* __restrict__ X,
                         const float* __restrict__ K,
                         float* __restrict__ O) {
    __shared__ __align__(16) float smem[SROWS * SWIDTH];

    const int tid  = threadIdx.x;
    const int tx   = tid & 127;
    const int tg   = tid >> 7;
    const int col  = tx << 2;
    const int img  = blockIdx.y;
    const int row0 = blockIdx.x << 3;          // CTA's first output row

    const float* in = X + (size_t)img * (IMG_W * IMG_H);
    char* sbase = reinterpret_cast<char*>(smem);

    // ---- Stage 1: burst-load tile (rows row0-2 .. row0+9), zero-filled OOB.
    // Image cols [4k,4k+4) -> cpad [4k+4,4k+8) -> byte 16k+16: aligned STS.128.
    #pragma unroll
    for (int i = 0; i < 6; i++) {
        const int q  = tid + (i << 8);
        const int r  = q >> 7;                  // 0..11
        const int k  = q & 127;                 // float4 index in row
        const int gr = row0 - 2 + r;
        float4 v = make_float4(0.f, 0.f, 0.f, 0.f);
        if (gr >= 0 && gr < IMG_H)
            v = *reinterpret_cast<const float4*>(in + (size_t)gr * IMG_W + (k << 2));
        *reinterpret_cast<float4*>(sbase + r * SROWB + (k << 4) + 16) = v;
    }
    // Halo columns: cpad [0,4) (byte 0) and cpad [516,520) (byte 2064): zeros.
    if (tid < 24) {
        const int r   = tid < 12 ? tid : tid - 12;
        const int off = tid < 12 ? 0 : (SPAD + IMG_W) * 4;
        *reinterpret_cast<float4*>(sbase + r * SROWB + off) =
            make_float4(0.f, 0.f, 0.f, 0.f);
    }

    // Broadcast-packed weights (w,w) x25 (overlaps the smem fill).
    u64 wp[25];
    {
        const float4* K4 = reinterpret_cast<const float4*>(K);
        #pragma unroll
        for (int i = 0; i < 6; i++) {
            float4 v = __ldg(K4 + i);
            wp[4*i+0] = pack2(v.x, v.x);
            wp[4*i+1] = pack2(v.y, v.y);
            wp[4*i+2] = pack2(v.z, v.z);
            wp[4*i+3] = pack2(v.w, v.w);
        }
        float w24 = __ldg(K + 24);
        wp[24] = pack2(w24, w24);
    }

    __syncthreads();

    // ---- Stage 2: conv from smem. Thread window = bytes [16tx+8, 16tx+40).
    u64 acc[4][2];
    #pragma unroll
    for (int ro = 0; ro < 4; ro++) { acc[ro][0] = 0ull; acc[ro][1] = 0ull; }

    const int cb = tx << 4;                    // thread window base byte
    #pragma unroll
    for (int lr = 0; lr < 8; lr++) {
        const char* rowp = sbase + ((tg << 2) + lr) * SROWB + cb;
        u64 p0 = *reinterpret_cast<const u64*>(rowp + 8);        // x[c-2],x[c-1]
        ulonglong2 Bq = *reinterpret_cast<const ulonglong2*>(rowp + 16);  // LDS.128
        u64 p2 = Bq.x;                                            // x[c],  x[c+1]
        u64 p4 = Bq.y;                                            // x[c+2],x[c+3]
        u64 p6 = *reinterpret_cast<const u64*>(rowp + 32);       // x[c+4],x[c+5]
        u64 p1 = pack_hl(p0, p2);
        u64 p3 = pack_hl(p2, p4);
        u64 p5 = pack_hl(p4, p6);
        u64 p[7] = {p0, p1, p2, p3, p4, p5, p6};

        // input row lr feeds output rows ro with kr = lr - ro in [0,4]
        #pragma unroll
        for (int ro = 0; ro < 4; ro++) {
            const int kr = lr - ro;
            if (kr < 0 || kr > 4) continue;
            #pragma unroll
            for (int kc = 0; kc < 5; kc++) {
                fma2(acc[ro][0], p[kc],     wp[kr*5 + kc]);  // (col, col+1)
                fma2(acc[ro][1], p[kc + 2], wp[kr*5 + kc]);  // (col+2, col+3)
            }
        }
    }

    float* op = O + (size_t)img * (IMG_W * IMG_H)
                  + (size_t)(row0 + (tg << 2)) * IMG_W + col;
    #pragma unroll
    for (int ro = 0; ro < 4; ro++) {
        ulonglong2 v;
        v.x = acc[ro][0];
        v.y = acc[ro][1];
        *reinterpret_cast<ulonglong2*>(op + (size_t)ro * IMG_W) = v;  // STG.128
    }
}

extern "C" void kernel_launch(void* const* d_in, const int* in_sizes, int n_in,
                              void* d_out, int out_size) {
    const float* X = (const float*)d_in[0];   // (4,32,512,512) f32
    const float* K = (const float*)d_in[1];   // (5,5) f32
    float* O = (float*)d_out;                 // (4,32,512,512) f32
    (void)in_sizes; (void)n_in; (void)out_size;  // stride=1, padding=2 fixed

    dim3 grid(IMG_H / TILE_OROWS, 4 * 32);    // 64 row tiles x 128 images
    conv5x5_smem_kernel<<<grid, 256>>>(X, K, O);
}

// round 14
// speedup vs baseline: 1.2570x; 1.0660x over previous
#include <cuda_runtime.h>
#include <cstdint>

typedef unsigned long long u64;

#define IMG_W 512
#define IMG_H 512

#define TILE_OROWS 8            // output rows per CTA
#define SROWS 12                // input rows staged (8 + 4 halo)
#define SPAD  2                 // left-pad floats: cpad = c + 2
#define SWIDTH 520              // floats per smem row (2080 B, 16B multiple)
#define SROWB (SWIDTH * 4)

// ---- f32x2 packed helpers ----
__device__ __forceinline__ u64 pack2(float lo, float hi) {
    u64 r;
    asm("mov.b64 %0, {%1, %2};"
        : "=l"(r) : "r"(__float_as_uint(lo)), "r"(__float_as_uint(hi)));
    return r;
}

__device__ __forceinline__ void fma2(u64& d, u64 a, u64 b) {
    asm("fma.rn.f32x2 %0, %1, %2, %0;" : "+l"(d) : "l"(a), "l"(b));
}

// (hi(a), lo(b)) -> odd-aligned sliding pair (2 MOVs in SASS).
__device__ __forceinline__ u64 pack_hl(u64 a, u64 b) {
    u64 d;
    asm("{\n\t"
        ".reg .b32 al, ah, bl, bh;\n\t"
        "mov.b64 {al, ah}, %1;\n\t"
        "mov.b64 {bl, bh}, %2;\n\t"
        "mov.b64 %0, {ah, bl};\n\t"
        "}" : "=l"(d) : "l"(a), "l"(b));
    return d;
}

// CTA: 256 threads. Tile rows shifted by 2 floats (cpad = c + 2) so that
// thread tx's read window [c-2, c+6) starts at byte 16*tx: the whole window
// is TWO conflict-free LDS.128s (8 crossbar phases/row/warp vs 16 before).
// Stage-1 pays with 2-way-conflicted STS.64 pairs, but stage 1 is 12 rows
// once vs stage 2's 8 rows x 8 warps. Thread: 4 out rows x 4 out cols.
__global__ __launch_bounds__(256)
void conv5x5_smem_kernel(const float* __restrict__ X,
                         const float* __restrict__ K,
                         float* __restrict__ O) {
    __shared__ __align__(16) float smem[SROWS * SWIDTH];

    const int tid  = threadIdx.x;
    const int tx   = tid & 127;
    const int tg   = tid >> 7;
    const int col  = tx << 2;
    const int img  = blockIdx.y;
    const int row0 = blockIdx.x << 3;          // CTA's first output row

    const float* in = X + (size_t)img * (IMG_W * IMG_H);
    char* sbase = reinterpret_cast<char*>(smem);

    // ---- Stage 1: burst-load tile (rows row0-2 .. row0+9), zero-filled OOB.
    // Image quad k -> cpad [4k+2, 4k+6) -> bytes [16k+8, 16k+24): 2x STS.64.
    #pragma unroll
    for (int i = 0; i < 6; i++) {
        const int q  = tid + (i << 8);
        const int r  = q >> 7;                  // 0..11
        const int k  = q & 127;                 // float4 index in row
        const int gr = row0 - 2 + r;
        float4 v = make_float4(0.f, 0.f, 0.f, 0.f);
        if (gr >= 0 && gr < IMG_H)
            v = *reinterpret_cast<const float4*>(in + (size_t)gr * IMG_W + (k << 2));
        char* rowp = sbase + r * SROWB + (k << 4);
        *reinterpret_cast<u64*>(rowp + 8)  = pack2(v.x, v.y);
        *reinterpret_cast<u64*>(rowp + 16) = pack2(v.z, v.w);
    }
    // Halo columns: cpad {0,1} (bytes 0-7) and {514,515} (bytes 2056-2063).
    if (tid < 24) {
        const int r   = tid < 12 ? tid : tid - 12;
        const int off = tid < 12 ? 0 : (SPAD + IMG_W) * 4;
        *reinterpret_cast<u64*>(sbase + r * SROWB + off) = 0ull;
    }

    // Broadcast-packed weights (w,w) x25 (overlaps the smem fill).
    u64 wp[25];
    {
        const float4* K4 = reinterpret_cast<const float4*>(K);
        #pragma unroll
        for (int i = 0; i < 6; i++) {
            float4 v = __ldg(K4 + i);
            wp[4*i+0] = pack2(v.x, v.x);
            wp[4*i+1] = pack2(v.y, v.y);
            wp[4*i+2] = pack2(v.z, v.z);
            wp[4*i+3] = pack2(v.w, v.w);
        }
        float w24 = __ldg(K + 24);
        wp[24] = pack2(w24, w24);
    }

    __syncthreads();

    // ---- Stage 2: conv from smem. Window = bytes [16tx, 16tx+32): 2 LDS.128.
    u64 acc[4][2];
    #pragma unroll
    for (int ro = 0; ro < 4; ro++) { acc[ro][0] = 0ull; acc[ro][1] = 0ull; }

    const int cb = tx << 4;
    #pragma unroll
    for (int lr = 0; lr < 8; lr++) {
        const char* rowp = sbase + ((tg << 2) + lr) * SROWB + cb;
        ulonglong2 A = *reinterpret_cast<const ulonglong2*>(rowp);       // p0,p2
        ulonglong2 B = *reinterpret_cast<const ulonglong2*>(rowp + 16);  // p4,p6
        u64 p0 = A.x, p2 = A.y, p4 = B.x, p6 = B.y;
        u64 p1 = pack_hl(p0, p2);
        u64 p3 = pack_hl(p2, p4);
        u64 p5 = pack_hl(p4, p6);
        u64 p[7] = {p0, p1, p2, p3, p4, p5, p6};

        // input row lr feeds output rows ro with kr = lr - ro in [0,4]
        #pragma unroll
        for (int ro = 0; ro < 4; ro++) {
            const int kr = lr - ro;
            if (kr < 0 || kr > 4) continue;
            #pragma unroll
            for (int kc = 0; kc < 5; kc++) {
                fma2(acc[ro][0], p[kc],     wp[kr*5 + kc]);  // (col, col+1)
                fma2(acc[ro][1], p[kc + 2], wp[kr*5 + kc]);  // (col+2, col+3)
            }
        }
    }

    float* op = O + (size_t)img * (IMG_W * IMG_H)
                  + (size_t)(row0 + (tg << 2)) * IMG_W + col;
    #pragma unroll
    for (int ro = 0; ro < 4; ro++) {
        ulonglong2 v;
        v.x = acc[ro][0];
        v.y = acc[ro][1];
        *reinterpret_cast<ulonglong2*>(op + (size_t)ro * IMG_W) = v;  // STG.128
    }
}

extern "C" void kernel_launch(void* const* d_in, const int* in_sizes, int n_in,
                              void* d_out, int out_size) {
    const float* X = (const float*)d_in[0];   // (4,32,512,512) f32
    const float* K = (const float*)d_in[1];   // (5,5) f32
    float* O = (float*)d_out;                 // (4,32,512,512) f32
    (void)in_sizes; (void)n_in; (void)out_size;  // stride=1, padding=2 fixed

    dim3 grid(IMG_H / TILE_OROWS, 4 * 32);    // 64 row tiles x 128 images
    conv5x5_smem_kernel<<<grid, 256>>>(X, K, O);
}

// round 15
// speedup vs baseline: 1.4036x; 1.1166x over previous
#include <cuda_runtime.h>
#include <cstdint>

typedef unsigned long long u64;

#define IMG_W 512
#define IMG_H 512

#define TILE_OROWS 16           // output rows per CTA
#define SROWS 20                // input rows staged (16 + 4 halo)
#define SPAD  2                 // left-pad floats: cpad = c + 2
#define SWIDTH 520              // floats per smem row (2080 B, 16B multiple)
#define SROWB (SWIDTH * 4)

// ---- f32x2 packed helpers ----
__device__ __forceinline__ u64 pack2(float lo, float hi) {
    u64 r;
    asm("mov.b64 %0, {%1, %2};"
        : "=l"(r) : "r"(__float_as_uint(lo)), "r"(__float_as_uint(hi)));
    return r;
}

__device__ __forceinline__ void fma2(u64& d, u64 a, u64 b) {
    asm("fma.rn.f32x2 %0, %1, %2, %0;" : "+l"(d) : "l"(a), "l"(b));
}

// (hi(a), lo(b)) -> odd-aligned sliding pair (2 MOVs in SASS).
__device__ __forceinline__ u64 pack_hl(u64 a, u64 b) {
    u64 d;
    asm("{\n\t"
        ".reg .b32 al, ah, bl, bh;\n\t"
        "mov.b64 {al, ah}, %1;\n\t"
        "mov.b64 {bl, bh}, %2;\n\t"
        "mov.b64 %0, {ah, bl};\n\t"
        "}" : "=l"(d) : "l"(a), "l"(b));
    return d;
}

// CTA: 256 threads = 128 col-threads x 2 row-groups; thread computes
// 8 output rows x 4 cols. 16-row tile halves the halo/LDS cost per output
// vs the 8-row tile: 12 input-row reads per 8 output rows (0.75 LDS-pairs
// per output row), 20 rows staged per 16 produced. Read window of thread tx
// starts at byte 16*tx -> two conflict-free LDS.128 per input row.
__global__ __launch_bounds__(256)
void conv5x5_smem_kernel(const float* __restrict__ X,
                         const float* __restrict__ K,
                         float* __restrict__ O) {
    __shared__ __align__(16) float smem[SROWS * SWIDTH];

    const int tid  = threadIdx.x;
    const int tx   = tid & 127;
    const int tg   = tid >> 7;
    const int col  = tx << 2;
    const int img  = blockIdx.y;
    const int row0 = blockIdx.x << 4;          // CTA's first output row

    const float* in = X + (size_t)img * (IMG_W * IMG_H);
    char* sbase = reinterpret_cast<char*>(smem);

    // ---- Stage 1: burst-load tile (rows row0-2 .. row0+17), zero-filled OOB.
    // Image quad k -> cpad [4k+2,4k+6) -> bytes [16k+8,16k+24): 2x STS.64.
    // 20 rows x 128 quads = 2560 quads; 256 threads x 10 iters.
    #pragma unroll
    for (int i = 0; i < 10; i++) {
        const int q  = tid + (i << 8);
        const int r  = q >> 7;                  // 0..19
        const int k  = q & 127;                 // float4 index in row
        const int gr = row0 - 2 + r;
        float4 v = make_float4(0.f, 0.f, 0.f, 0.f);
        if (gr >= 0 && gr < IMG_H)
            v = *reinterpret_cast<const float4*>(in + (size_t)gr * IMG_W + (k << 2));
        char* rowp = sbase + r * SROWB + (k << 4);
        *reinterpret_cast<u64*>(rowp + 8)  = pack2(v.x, v.y);
        *reinterpret_cast<u64*>(rowp + 16) = pack2(v.z, v.w);
    }
    // Halo columns: cpad {0,1} (bytes 0-7) and {514,515} (bytes 2056-2063).
    if (tid < 2 * SROWS) {
        const int r   = tid < SROWS ? tid : tid - SROWS;
        const int off = tid < SROWS ? 0 : (SPAD + IMG_W) * 4;
        *reinterpret_cast<u64*>(sbase + r * SROWB + off) = 0ull;
    }

    // Broadcast-packed weights (w,w) x25 (overlaps the smem fill).
    u64 wp[25];
    {
        const float4* K4 = reinterpret_cast<const float4*>(K);
        #pragma unroll
        for (int i = 0; i < 6; i++) {
            float4 v = __ldg(K4 + i);
            wp[4*i+0] = pack2(v.x, v.x);
            wp[4*i+1] = pack2(v.y, v.y);
            wp[4*i+2] = pack2(v.z, v.z);
            wp[4*i+3] = pack2(v.w, v.w);
        }
        float w24 = __ldg(K + 24);
        wp[24] = pack2(w24, w24);
    }

    __syncthreads();

    // ---- Stage 2: thread's output rows = row0 + tg*8 + 0..7; input rows
    // tg*8 + lr for lr in 0..11. Window = bytes [16tx, 16tx+32): 2 LDS.128.
    u64 acc[8][2];
    #pragma unroll
    for (int ro = 0; ro < 8; ro++) { acc[ro][0] = 0ull; acc[ro][1] = 0ull; }

    const int cb = tx << 4;
    #pragma unroll
    for (int lr = 0; lr < 12; lr++) {
        const char* rowp = sbase + ((tg << 3) + lr) * SROWB + cb;
        ulonglong2 A = *reinterpret_cast<const ulonglong2*>(rowp);       // p0,p2
        ulonglong2 B = *reinterpret_cast<const ulonglong2*>(rowp + 16);  // p4,p6
        u64 p0 = A.x, p2 = A.y, p4 = B.x, p6 = B.y;
        u64 p1 = pack_hl(p0, p2);
        u64 p3 = pack_hl(p2, p4);
        u64 p5 = pack_hl(p4, p6);
        u64 p[7] = {p0, p1, p2, p3, p4, p5, p6};

        // input row lr feeds output rows ro with kr = lr - ro in [0,4]
        #pragma unroll
        for (int ro = 0; ro < 8; ro++) {
            const int kr = lr - ro;
            if (kr < 0 || kr > 4) continue;
            #pragma unroll
            for (int kc = 0; kc < 5; kc++) {
                fma2(acc[ro][0], p[kc],     wp[kr*5 + kc]);  // (col, col+1)
                fma2(acc[ro][1], p[kc + 2], wp[kr*5 + kc]);  // (col+2, col+3)
            }
        }
    }

    float* op = O + (size_t)img * (IMG_W * IMG_H)
                  + (size_t)(row0 + (tg << 3)) * IMG_W + col;
    #pragma unroll
    for (int ro = 0; ro < 8; ro++) {
        ulonglong2 v;
        v.x = acc[ro][0];
        v.y = acc[ro][1];
        *reinterpret_cast<ulonglong2*>(op + (size_t)ro * IMG_W) = v;  // STG.128
    }
}

extern "C" void kernel_launch(void* const* d_in, const int* in_sizes, int n_in,
                              void* d_out, int out_size) {
    const float* X = (const float*)d_in[0];   // (4,32,512,512) f32
    const float* K = (const float*)d_in[1];   // (5,5) f32
    float* O = (float*)d_out;                 // (4,32,512,512) f32
    (void)in_sizes; (void)n_in; (void)out_size;  // stride=1, padding=2 fixed

    dim3 grid(IMG_H / TILE_OROWS, 4 * 32);    // 32 row tiles x 128 images
    conv5x5_smem_kernel<<<grid, 256>>>(X, K, O);
}